// round 9
// baseline (speedup 1.0000x reference)
#include <cuda_runtime.h>
#include <cuda_bf16.h>
#include <cstdint>

#define B_   32
#define NA   512
#define NV   256
#define D_   384
#define BM   128
#define BN   256
#define BKE  64                     // bf16 elements per k-chunk (4 k16 slices)
#define NCH  (D_ / BKE)             // 6
#define NSTG 3

#define A_SLICE  (BM * 32)          // 4096 B  (one k16 slice of A)
#define B_SLICE  (BN * 32)          // 8192 B
#define A_TILE   (4 * A_SLICE)      // 16384 B
#define B_TILE   (4 * B_SLICE)      // 32768 B
#define STAGE_B  (A_TILE + B_TILE)  // 49152 B
#define SMEM_BYTES (NSTG * STAGE_B) // 147456 B

#define NTHREADS 512

// bf16 scratch (device globals: allocation-free)
__device__ __align__(16) __nv_bfloat16 g_audio_bf[B_ * NA * D_];   // 12.6 MB
__device__ __align__(16) __nv_bfloat16 g_visual_bf[B_ * NV * D_];  //  6.3 MB

// ---------------- helpers ----------------
__device__ __forceinline__ uint32_t smem_u32(const void* p) {
    uint32_t a;
    asm("{ .reg .u64 t; cvta.to.shared.u64 t, %1; cvt.u32.u64 %0, t; }" : "=r"(a) : "l"(p));
    return a;
}
#define CP_ASYNC16(dst, src) \
    asm volatile("cp.async.cg.shared.global [%0], [%1], 16;" :: "r"(dst), "l"(src) : "memory")
#define CP_COMMIT()  asm volatile("cp.async.commit_group;" ::: "memory")
#define CP_WAIT(N)   asm volatile("cp.async.wait_group %0;" :: "n"(N) : "memory")

#define LDSM_X4(r, addr) \
    asm volatile("ldmatrix.sync.aligned.m8n8.x4.shared.b16 {%0,%1,%2,%3}, [%4];" \
                 : "=r"((r)[0]), "=r"((r)[1]), "=r"((r)[2]), "=r"((r)[3]) : "r"(addr))

__device__ __forceinline__ void mma_bf16(float* d, const uint32_t* a, const uint32_t* b) {
    asm volatile(
        "mma.sync.aligned.m16n8k16.row.col.f32.bf16.bf16.f32 "
        "{%0,%1,%2,%3}, {%4,%5,%6,%7}, {%8,%9}, {%0,%1,%2,%3};"
        : "+f"(d[0]), "+f"(d[1]), "+f"(d[2]), "+f"(d[3])
        : "r"(a[0]), "r"(a[1]), "r"(a[2]), "r"(a[3]), "r"(b[0]), "r"(b[1]));
}

__device__ __forceinline__ void lse_comb(float& m, float& s, int o) {
    float om = __shfl_xor_sync(0xffffffffu, m, o);
    float os = __shfl_xor_sync(0xffffffffu, s, o);
    float mn = fmaxf(m, om);
    s = s * __expf((m - mn) * 0.5f) + os * __expf((om - mn) * 0.5f);
    m = mn;
}

// ---------------- fp32 -> bf16 conversion ----------------
__global__ void cvt_bf16_kernel(const float* __restrict__ audio,
                                const float* __restrict__ visual) {
    const int NAE = B_ * NA * D_;
    const int NVE = B_ * NV * D_;
    int stride = gridDim.x * blockDim.x;
    for (int t = blockIdx.x * blockDim.x + threadIdx.x; t < NAE / 4; t += stride) {
        float4 v = reinterpret_cast<const float4*>(audio)[t];
        __nv_bfloat162 p0 = __floats2bfloat162_rn(v.x, v.y);
        __nv_bfloat162 p1 = __floats2bfloat162_rn(v.z, v.w);
        reinterpret_cast<uint2*>(g_audio_bf)[t] =
            make_uint2(*reinterpret_cast<uint32_t*>(&p0), *reinterpret_cast<uint32_t*>(&p1));
    }
    for (int t = blockIdx.x * blockDim.x + threadIdx.x; t < NVE / 4; t += stride) {
        float4 v = reinterpret_cast<const float4*>(visual)[t];
        __nv_bfloat162 p0 = __floats2bfloat162_rn(v.x, v.y);
        __nv_bfloat162 p1 = __floats2bfloat162_rn(v.z, v.w);
        reinterpret_cast<uint2*>(g_visual_bf)[t] =
            make_uint2(*reinterpret_cast<uint32_t*>(&p0), *reinterpret_cast<uint32_t*>(&p1));
    }
}

// ---------------- main fused kernel ----------------
__global__ void __launch_bounds__(NTHREADS, 1)
mm_bf16_lse_kernel(float* __restrict__ out) {
    extern __shared__ char smem[];
    const uint32_t sb = smem_u32(smem);
    const int tid   = threadIdx.x;
    const int warp  = tid >> 5;
    const int lane  = tid & 31;
    const int warpm = warp >> 2;        // 0..3 -> 32-row strip
    const int warpn = warp & 3;         // 0..3 -> 64-col quarter
    const int g     = lane >> 2;        // 0..7
    const int c     = lane & 3;         // 0..3

    const int mt_b = blockIdx.x;        // 0..3
    const int j    = blockIdx.y;        // visual batch
    const int i    = blockIdx.z;        // audio batch

    const __nv_bfloat16* Ab = g_audio_bf  + ((size_t)i * NA + (size_t)mt_b * BM) * D_;
    const __nv_bfloat16* Vb = g_visual_bf + (size_t)j * NV * D_;

    float acc[2][8][4];
    #pragma unroll
    for (int mt = 0; mt < 2; mt++)
        #pragma unroll
        for (int nt = 0; nt < 8; nt++)
            #pragma unroll
            for (int e = 0; e < 4; e++) acc[mt][nt][e] = 0.f;

    // ---- stage loader: k-sliced layout [slice][row][32B], 16B-half swizzle ----
    // granule idx -> half = idx&1, row = (idx>>1)&(rows-1), slice = idx >> log2(rows*2)
    auto load_stage = [&](int s, int kc) {
        const uint32_t a_off = s * STAGE_B;
        const uint32_t b_off = a_off + A_TILE;
        const int kb = kc * BKE;
        #pragma unroll
        for (int e = 0; e < 2; e++) {             // A: 4 slices x 128 rows x 2 halves = 1024
            int idx   = e * NTHREADS + tid;
            int half  = idx & 1;
            int row   = (idx >> 1) & 127;
            int slice = idx >> 8;
            uint32_t dst = sb + a_off + slice * A_SLICE + row * 32
                         + ((half * 16) ^ ((row & 4) ? 16 : 0));
            CP_ASYNC16(dst, Ab + (size_t)row * D_ + kb + slice * 16 + half * 8);
        }
        #pragma unroll
        for (int e = 0; e < 4; e++) {             // B: 4 slices x 256 rows x 2 halves = 2048
            int idx   = e * NTHREADS + tid;
            int half  = idx & 1;
            int row   = (idx >> 1) & 255;
            int slice = idx >> 9;
            uint32_t dst = sb + b_off + slice * B_SLICE + row * 32
                         + ((half * 16) ^ ((row & 4) ? 16 : 0));
            CP_ASYNC16(dst, Vb + (size_t)row * D_ + kb + slice * 16 + half * 8);
        }
        CP_COMMIT();
    };

    // ---- per-lane LDSM base offsets (within a slice) ----
    // A: lanes 0-15 -> rows (lane&15) half0 ; lanes 16-31 -> same rows half1
    const uint32_t a_r   = (uint32_t)(lane & 15);
    const uint32_t a_ln  = (uint32_t)(warpm * 32 + a_r) * 32
                         + ((((uint32_t)(lane >> 4) & 1) * 16) ^ ((a_r & 4) ? 16u : 0u));
    // B: row16 = (lane&7)|((lane&16)>>1), half = (lane>>3)&1
    const uint32_t b_r   = (uint32_t)((lane & 7) | ((lane & 16) >> 1));
    const uint32_t b_ln  = (uint32_t)(warpn * 64 + b_r) * 32
                         + ((((uint32_t)(lane >> 3) & 1) * 16) ^ ((b_r & 4) ? 16u : 0u));

    auto compute = [&](int s) {
        const uint32_t a_s = sb + s * STAGE_B + a_ln;           // + ks*A_SLICE + mt*512
        const uint32_t b_s = sb + s * STAGE_B + A_TILE + b_ln;  // + ks*B_SLICE + p*512
        uint32_t bf[2][4][4];
        #pragma unroll
        for (int p = 0; p < 4; p++) LDSM_X4(bf[0][p], b_s + p * 512);   // prefetch ks=0
        #pragma unroll
        for (int ks = 0; ks < 4; ks++) {
            uint32_t af[2][4];
            #pragma unroll
            for (int mt = 0; mt < 2; mt++)
                LDSM_X4(af[mt], a_s + ks * A_SLICE + mt * 512);
            if (ks < 3) {
                #pragma unroll
                for (int p = 0; p < 4; p++)
                    LDSM_X4(bf[(ks + 1) & 1][p], b_s + (ks + 1) * B_SLICE + p * 512);
            }
            #pragma unroll
            for (int mt = 0; mt < 2; mt++)
                #pragma unroll
                for (int p = 0; p < 4; p++) {
                    mma_bf16(acc[mt][2 * p],     af[mt], &bf[ks & 1][p][0]);
                    mma_bf16(acc[mt][2 * p + 1], af[mt], &bf[ks & 1][p][2]);
                }
        }
    };

    // ---- 3-stage pipelined mainloop: one barrier per chunk ----
    load_stage(0, 0);
    load_stage(1, 1);
    load_stage(2, 2);
    #pragma unroll
    for (int kc = 0; kc < NCH; kc++) {
        if (kc == 0)            { CP_WAIT(2); }
        else if (kc < NCH - 1)  { CP_WAIT(1); }
        else                    { CP_WAIT(0); }
        __syncthreads();
        if (kc >= 1 && kc + 2 < NCH) load_stage((kc + 2) % NSTG, kc + 2);
        compute(kc % NSTG);
    }

    // ---- epilogue: tau*logsumexp over 256 cols, mean over rows ----
    __syncthreads();
    float* pmax = reinterpret_cast<float*>(smem);          // [128][4]
    float* psum = pmax + 512;                              // [128][4]
    float* wsum = pmax + 1024;                             // [4]

    #pragma unroll
    for (int mt = 0; mt < 2; mt++) {
        int r0 = warpm * 32 + mt * 16 + g;
        float m0 = -1e30f, m1 = -1e30f;
        #pragma unroll
        for (int nt = 0; nt < 8; nt++) {
            m0 = fmaxf(m0, fmaxf(acc[mt][nt][0], acc[mt][nt][1]));
            m1 = fmaxf(m1, fmaxf(acc[mt][nt][2], acc[mt][nt][3]));
        }
        float s0 = 0.f, s1 = 0.f;
        #pragma unroll
        for (int nt = 0; nt < 8; nt++) {
            s0 += __expf((acc[mt][nt][0] - m0) * 0.5f) + __expf((acc[mt][nt][1] - m0) * 0.5f);
            s1 += __expf((acc[mt][nt][2] - m1) * 0.5f) + __expf((acc[mt][nt][3] - m1) * 0.5f);
        }
        lse_comb(m0, s0, 1); lse_comb(m0, s0, 2);
        lse_comb(m1, s1, 1); lse_comb(m1, s1, 2);
        if (c == 0) {
            pmax[(r0)     * 4 + warpn] = m0;  psum[(r0)     * 4 + warpn] = s0;
            pmax[(r0 + 8) * 4 + warpn] = m1;  psum[(r0 + 8) * 4 + warpn] = s1;
        }
    }
    __syncthreads();

    if (tid < 128) {
        float m = pmax[tid * 4];
        #pragma unroll
        for (int w = 1; w < 4; w++) m = fmaxf(m, pmax[tid * 4 + w]);
        float s = 0.f;
        #pragma unroll
        for (int w = 0; w < 4; w++) s += psum[tid * 4 + w] * __expf((pmax[tid * 4 + w] - m) * 0.5f);
        float lse = m + 2.0f * __logf(s);
        #pragma unroll
        for (int o = 16; o > 0; o >>= 1) lse += __shfl_xor_sync(0xffffffffu, lse, o);
        if (lane == 0) wsum[warp] = lse;
    }
    __syncthreads();
    if (tid == 0) {
        float t = wsum[0] + wsum[1] + wsum[2] + wsum[3];
        atomicAdd(&out[i * B_ + j], t * (1.0f / NA));
    }
}

// ---------------- launch ----------------
extern "C" void kernel_launch(void* const* d_in, const int* in_sizes, int n_in,
                              void* d_out, int out_size) {
    const float* audio  = (const float*)d_in[0];   // (32, 512, 384) fp32
    const float* visual = (const float*)d_in[1];   // (32, 256, 384) fp32
    float* out = (float*)d_out;                    // (32, 32) fp32

    cudaFuncSetAttribute(mm_bf16_lse_kernel,
                         cudaFuncAttributeMaxDynamicSharedMemorySize, SMEM_BYTES);

    cudaMemsetAsync(out, 0, (size_t)out_size * sizeof(float));
    cvt_bf16_kernel<<<1184, 256>>>(audio, visual);

    dim3 grid(NA / BM, B_, B_);   // (4, 32, 32)
    mm_bf16_lse_kernel<<<grid, NTHREADS, SMEM_BYTES>>>(out);
}